// round 15
// baseline (speedup 1.0000x reference)
#include <cuda_runtime.h>
#include <cuda_bf16.h>
#include <math.h>
#include <stdint.h>

#define N_NODES   20000
#define N_EDGES   320000
#define NUM_GRAPHS 64
#define D0 256   // input dim
#define D1 256   // hidden 1
#define D2 128   // hidden 2

// ---------------- device scratch (static globals; no runtime alloc) ----------------
__device__ __align__(16) int   g_deg[N_NODES];
__device__ __align__(16) int   g_csr_off[N_NODES + 1];
__device__ __align__(16) int   g_csr_cur[N_NODES];
__device__ __align__(16) int2  g_edge[N_EDGES];              // {src, dinv[src] bits}
__device__ __align__(16) float g_dinv[N_NODES];
__device__ __align__(16) float g_h1[(size_t)N_NODES * D1];
__device__ __align__(16) float g_z1[(size_t)N_NODES * D1];
__device__ __align__(16) float g_h2[(size_t)N_NODES * D2];
__device__ __align__(16) float g_gsum[NUM_GRAPHS * D2];
__device__ __align__(16) int   g_gcnt[NUM_GRAPHS];

// ---------------- degree histogram over dst, 4 edges/thread ----------------
__global__ void count_kernel(const int* __restrict__ ei) {
    int i = blockIdx.x * blockDim.x + threadIdx.x;
    if (i < N_EDGES / 4) {
        int4 d = __ldg(reinterpret_cast<const int4*>(ei + N_EDGES) + i);
        atomicAdd(&g_deg[d.x], 1);
        atomicAdd(&g_deg[d.y], 1);
        atomicAdd(&g_deg[d.z], 1);
        atomicAdd(&g_deg[d.w], 1);
    }
}

// ---------------- single-block warp-shuffle scan ----------------
__global__ void scan_kernel() {
    __shared__ int warp_sums[32];
    int tid = threadIdx.x;            // 1024 threads
    int lane = tid & 31, wid = tid >> 5;
    int carry = 0;
    for (int base = 0; base < N_NODES; base += 1024) {
        int i = base + tid;
        int v = (i < N_NODES) ? g_deg[i] : 0;
        int x = v;
        #pragma unroll
        for (int off = 1; off < 32; off <<= 1) {
            int y = __shfl_up_sync(0xffffffffu, x, off);
            if (lane >= off) x += y;
        }
        if (lane == 31) warp_sums[wid] = x;
        __syncthreads();
        if (wid == 0) {
            int w = warp_sums[lane];
            #pragma unroll
            for (int off = 1; off < 32; off <<= 1) {
                int y = __shfl_up_sync(0xffffffffu, w, off);
                if (lane >= off) w += y;
            }
            warp_sums[lane] = w;
        }
        __syncthreads();
        int warp_prefix = (wid > 0) ? warp_sums[wid - 1] : 0;
        int incl = carry + warp_prefix + x;
        if (i < N_NODES) {
            g_csr_off[i + 1] = incl;
            g_csr_cur[i]     = incl - v;
            g_dinv[i]        = rsqrtf((float)(v + 1));
        }
        if (i == 0) g_csr_off[0] = 0;
        int tot = warp_sums[31];
        __syncthreads();
        carry += tot;
    }
}

// ---------------- CSR fill: 4 edges/thread, packed {src, w} per slot ----------------
__global__ void fill_kernel(const int* __restrict__ ei) {
    int i = blockIdx.x * blockDim.x + threadIdx.x;
    if (i < N_EDGES / 4) {
        int4 s4 = __ldg(reinterpret_cast<const int4*>(ei) + i);
        int4 d4 = __ldg(reinterpret_cast<const int4*>(ei + N_EDGES) + i);
        int slot;
        slot = atomicAdd(&g_csr_cur[d4.x], 1);
        g_edge[slot] = make_int2(s4.x, __float_as_int(g_dinv[s4.x]));
        slot = atomicAdd(&g_csr_cur[d4.y], 1);
        g_edge[slot] = make_int2(s4.y, __float_as_int(g_dinv[s4.y]));
        slot = atomicAdd(&g_csr_cur[d4.z], 1);
        g_edge[slot] = make_int2(s4.z, __float_as_int(g_dinv[s4.z]));
        slot = atomicAdd(&g_csr_cur[d4.w], 1);
        g_edge[slot] = make_int2(s4.w, __float_as_int(g_dinv[s4.w]));
    }
}

// ======= bf16 tensor-core GEMM (mma.sync m16n8k16), templated tile: C(f32) = A @ B =======
#define ASTR 20   // As word stride: A-frag LDS conflict-free, v2 STS aligned
#define BSTR 21   // Bs word stride: transpose STS conflict-free

template<int BM, int BN, int WGM, int WGN>
__global__ __launch_bounds__(256, 2)
void gemm_bf16_kernel(const float* __restrict__ A, const float* __restrict__ B,
                      float* __restrict__ C, int M, int N, int K) {
    constexpr int MT = BM / (WGM * 16);   // m16 tiles per warp
    constexpr int NT = BN / (WGN * 8);    // n8 tiles per warp
    __shared__ uint32_t As[BM * ASTR];    // [row][k2] bf16x2, k2 = 0..15
    __shared__ uint32_t Bs[BN * BSTR];    // [col][k2] bf16x2 (transposed)

    int tid  = threadIdx.x;               // 256
    int lane = tid & 31, wid = tid >> 5;  // 8 warps
    int wm = wid % WGM, wn = wid / WGM;
    int warp_row = wm * (BM / WGM);
    int warp_col = wn * (BN / WGN);
    int row0 = blockIdx.x * BM;
    int col0 = blockIdx.y * BN;
    int tig = lane & 3, grp = lane >> 2;

    float acc[MT][NT][4] = {};

    for (int k0 = 0; k0 < K; k0 += 32) {
        // ---- A chunk: BM rows x 32 cols fp32 -> bf16x2
        #pragma unroll
        for (int i = 0; i < BM * 8 / 256; i++) {
            int idx = tid + (i << 8);
            int r  = idx >> 3;
            int c4 = (idx & 7) << 2;
            int gr = row0 + r;
            float4 v = make_float4(0.f, 0.f, 0.f, 0.f);
            if (gr < M) v = *reinterpret_cast<const float4*>(&A[(size_t)gr * K + k0 + c4]);
            __nv_bfloat162 p0 = __float22bfloat162_rn(make_float2(v.x, v.y));
            __nv_bfloat162 p1 = __float22bfloat162_rn(make_float2(v.z, v.w));
            *reinterpret_cast<uint2*>(&As[r * ASTR + (c4 >> 1)]) =
                make_uint2(*reinterpret_cast<uint32_t*>(&p0), *reinterpret_cast<uint32_t*>(&p1));
        }
        // ---- B chunk transposed: Bs[n][k2] = {B[k0+2k2][n], B[k0+2k2+1][n]}
        #pragma unroll
        for (int i = 0; i < BN * 16 / 256; i++) {
            int idx = tid + (i << 8);
            int k2 = idx / BN;
            int n  = idx % BN;
            const float* bp = &B[(size_t)(k0 + 2 * k2) * N + col0 + n];
            __nv_bfloat162 p = __float22bfloat162_rn(make_float2(bp[0], bp[N]));
            Bs[n * BSTR + k2] = *reinterpret_cast<uint32_t*>(&p);
        }
        __syncthreads();

        #pragma unroll
        for (int ks = 0; ks < 2; ks++) {  // two k16 steps per chunk
            int kw = ks << 3;
            uint32_t af[MT][4], bf[NT][2];
            #pragma unroll
            for (int mt = 0; mt < MT; mt++) {
                int r = warp_row + mt * 16 + grp;
                af[mt][0] = As[r * ASTR + kw + tig];
                af[mt][1] = As[(r + 8) * ASTR + kw + tig];
                af[mt][2] = As[r * ASTR + kw + tig + 4];
                af[mt][3] = As[(r + 8) * ASTR + kw + tig + 4];
            }
            #pragma unroll
            for (int nt = 0; nt < NT; nt++) {
                int c = warp_col + nt * 8 + grp;
                bf[nt][0] = Bs[c * BSTR + kw + tig];
                bf[nt][1] = Bs[c * BSTR + kw + tig + 4];
            }
            #pragma unroll
            for (int mt = 0; mt < MT; mt++)
                #pragma unroll
                for (int nt = 0; nt < NT; nt++) {
                    asm volatile(
                        "mma.sync.aligned.m16n8k16.row.col.f32.bf16.bf16.f32 "
                        "{%0,%1,%2,%3}, {%4,%5,%6,%7}, {%8,%9}, {%0,%1,%2,%3};\n"
                        : "+f"(acc[mt][nt][0]), "+f"(acc[mt][nt][1]),
                          "+f"(acc[mt][nt][2]), "+f"(acc[mt][nt][3])
                        : "r"(af[mt][0]), "r"(af[mt][1]), "r"(af[mt][2]), "r"(af[mt][3]),
                          "r"(bf[nt][0]), "r"(bf[nt][1]));
                }
        }
        __syncthreads();
    }

    // epilogue: c0/c1 at (row, 2*tig), c2/c3 at (row+8, 2*tig)
    #pragma unroll
    for (int mt = 0; mt < MT; mt++) {
        int r_lo = row0 + warp_row + mt * 16 + grp;
        int r_hi = r_lo + 8;
        #pragma unroll
        for (int nt = 0; nt < NT; nt++) {
            int c = col0 + warp_col + nt * 8 + 2 * tig;
            if (r_lo < M) {
                float2 v = make_float2(acc[mt][nt][0], acc[mt][nt][1]);
                *reinterpret_cast<float2*>(&C[(size_t)r_lo * N + c]) = v;
            }
            if (r_hi < M) {
                float2 v = make_float2(acc[mt][nt][2], acc[mt][nt][3]);
                *reinterpret_cast<float2*>(&C[(size_t)r_hi * N + c]) = v;
            }
        }
    }
}

// ---------------- gather aggregation (float4, packed edges, unroll-2) ----------------
template <int F, bool POOL>
__global__ void aggregate_kernel(const float* __restrict__ H, const float* __restrict__ bias,
                                 float* __restrict__ Z, const int* __restrict__ batch) {
    constexpr int TF  = F / 4;
    constexpr int NPB = 256 / TF;
    int node = blockIdx.x * NPB + threadIdx.y;
    if (node >= N_NODES) return;
    int t = threadIdx.x;
    const float4* H4 = reinterpret_cast<const float4*>(H);

    float di = g_dinv[node];
    float4 h = __ldg(&H4[(size_t)node * TF + t]);
    float4 acc = make_float4(di * h.x, di * h.y, di * h.z, di * h.w);

    int e = g_csr_off[node], e1 = g_csr_off[node + 1];
    for (; e + 1 < e1; e += 2) {
        int2 r0 = __ldg(&g_edge[e]);
        int2 r1 = __ldg(&g_edge[e + 1]);
        float4 h0 = __ldg(&H4[(size_t)r0.x * TF + t]);
        float4 h1 = __ldg(&H4[(size_t)r1.x * TF + t]);
        float w0 = __int_as_float(r0.y), w1 = __int_as_float(r1.y);
        acc.x = fmaf(w0, h0.x, fmaf(w1, h1.x, acc.x));
        acc.y = fmaf(w0, h0.y, fmaf(w1, h1.y, acc.y));
        acc.z = fmaf(w0, h0.z, fmaf(w1, h1.z, acc.z));
        acc.w = fmaf(w0, h0.w, fmaf(w1, h1.w, acc.w));
    }
    if (e < e1) {
        int2 r0 = __ldg(&g_edge[e]);
        float4 h0 = __ldg(&H4[(size_t)r0.x * TF + t]);
        float w0 = __int_as_float(r0.y);
        acc.x = fmaf(w0, h0.x, acc.x);
        acc.y = fmaf(w0, h0.y, acc.y);
        acc.z = fmaf(w0, h0.z, acc.z);
        acc.w = fmaf(w0, h0.w, acc.w);
    }
    float4 b4 = __ldg(&reinterpret_cast<const float4*>(bias)[t]);
    float4 v;
    v.x = fmaxf(fmaf(di, acc.x, b4.x), 0.0f);
    v.y = fmaxf(fmaf(di, acc.y, b4.y), 0.0f);
    v.z = fmaxf(fmaf(di, acc.z, b4.z), 0.0f);
    v.w = fmaxf(fmaf(di, acc.w, b4.w), 0.0f);

    if (POOL) {
        int g = batch[node];
        float* gp = &g_gsum[g * F + 4 * t];
        atomicAdd(gp + 0, v.x);
        atomicAdd(gp + 1, v.y);
        atomicAdd(gp + 2, v.z);
        atomicAdd(gp + 3, v.w);
        if (t == 0) atomicAdd(&g_gcnt[g], 1);
    } else {
        reinterpret_cast<float4*>(Z)[(size_t)node * TF + t] = v;
    }
}

// ---------------- head MLP ----------------
__global__ void final_kernel(const float* __restrict__ Wl1, const float* __restrict__ bl1,
                             const float* __restrict__ Wl2, const float* __restrict__ bl2,
                             float* __restrict__ out) {
    int g = blockIdx.x;
    int j = threadIdx.x;    // 64
    __shared__ float sg[D2];
    __shared__ float sr[64];
    float cnt = (float)max(g_gcnt[g], 1);
    for (int k = j; k < D2; k += 64) sg[k] = g_gsum[g * D2 + k] / cnt;
    __syncthreads();
    float acc = bl1[j];
    #pragma unroll 8
    for (int k = 0; k < D2; k++) acc = fmaf(sg[k], Wl1[k * 64 + j], acc);
    acc = fmaxf(acc, 0.0f);
    sr[j] = acc * Wl2[j];
    #pragma unroll
    for (int off = 32; off > 0; off >>= 1) {
        __syncthreads();
        if (j < off) sr[j] += sr[j + off];
    }
    __syncthreads();
    if (j == 0) out[g] = 1.0f / (1.0f + expf(-(sr[0] + bl2[0])));
}

// ---------------- launch: fork CSR build || GEMM1, join before agg1 ----------------
extern "C" void kernel_launch(void* const* d_in, const int* in_sizes, int n_in,
                              void* d_out, int out_size) {
    const float* x     = (const float*)d_in[0];
    const int*   ei    = (const int*)d_in[1];     // int32 (JAX x64 disabled)
    const int*   batch = (const int*)d_in[2];     // int32
    const float* W1  = (const float*)d_in[3];
    const float* b1  = (const float*)d_in[4];
    const float* W2  = (const float*)d_in[5];
    const float* b2  = (const float*)d_in[6];
    const float* Wl1 = (const float*)d_in[7];
    const float* bl1 = (const float*)d_in[8];
    const float* Wl2 = (const float*)d_in[9];
    const float* bl2 = (const float*)d_in[10];
    float* out = (float*)d_out;

    void* p;
    cudaGetSymbolAddress(&p, g_h1);   float* h1 = (float*)p;
    cudaGetSymbolAddress(&p, g_z1);   float* z1 = (float*)p;
    cudaGetSymbolAddress(&p, g_h2);   float* h2 = (float*)p;
    cudaGetSymbolAddress(&p, g_deg);  void* degp = p;
    cudaGetSymbolAddress(&p, g_gsum); void* gsump = p;
    cudaGetSymbolAddress(&p, g_gcnt); void* gcntp = p;

    static cudaStream_t s1 = nullptr;
    static cudaEvent_t evFork = nullptr, evJoin = nullptr;
    if (s1 == nullptr) {
        cudaStreamCreateWithFlags(&s1, cudaStreamNonBlocking);
        cudaEventCreateWithFlags(&evFork, cudaEventDisableTiming);
        cudaEventCreateWithFlags(&evJoin, cudaEventDisableTiming);
    }

    // fork
    cudaEventRecord(evFork, 0);
    cudaStreamWaitEvent(s1, evFork, 0);

    // s1: CSR build chain (memsets replace init kernel)
    cudaMemsetAsync(degp, 0, N_NODES * sizeof(int), s1);
    cudaMemsetAsync(gsump, 0, NUM_GRAPHS * D2 * sizeof(float), s1);
    cudaMemsetAsync(gcntp, 0, NUM_GRAPHS * sizeof(int), s1);
    count_kernel<<<(N_EDGES / 4 + 255) / 256, 256, 0, s1>>>(ei);
    scan_kernel<<<1, 1024, 0, s1>>>();
    fill_kernel<<<(N_EDGES / 4 + 255) / 256, 256, 0, s1>>>(ei);
    cudaEventRecord(evJoin, s1);

    // main: GEMM1 (128x64 tiles -> 157x4 = 628 CTAs, no wave tail)
    gemm_bf16_kernel<128, 64, 4, 2><<<dim3((N_NODES + 127) / 128, D1 / 64), 256>>>(
        x, W1, h1, N_NODES, D1, D0);

    // join: agg1 needs both CSR and h1
    cudaStreamWaitEvent(0, evJoin, 0);

    {
        dim3 blk(D1 / 4, 256 / (D1 / 4));         // (64, 4)
        aggregate_kernel<D1, false><<<(N_NODES + 3) / 4, blk>>>(h1, b1, z1, nullptr);
    }

    // GEMM2 (64x64 tiles -> 313x2 = 626 CTAs)
    gemm_bf16_kernel<64, 64, 4, 2><<<dim3((N_NODES + 63) / 64, D2 / 64), 256>>>(
        z1, W2, h2, N_NODES, D2, D1);

    {
        dim3 blk(D2 / 4, 256 / (D2 / 4));         // (32, 8)
        aggregate_kernel<D2, true><<<(N_NODES + 7) / 8, blk>>>(h2, b2, nullptr, batch);
    }

    final_kernel<<<NUM_GRAPHS, 64>>>(Wl1, bl1, Wl2, bl2, out);
}

// round 16
// speedup vs baseline: 1.1604x; 1.1604x over previous
#include <cuda_runtime.h>
#include <cuda_bf16.h>
#include <math.h>
#include <stdint.h>

#define N_NODES   20000
#define N_EDGES   320000
#define NUM_GRAPHS 64
#define D0 256   // input dim
#define D1 256   // hidden 1
#define D2 128   // hidden 2

// ---------------- device scratch (static globals; no runtime alloc) ----------------
__device__ __align__(16) int   g_deg[N_NODES];
__device__ __align__(16) int   g_csr_off[N_NODES + 1];
__device__ __align__(16) int   g_csr_cur[N_NODES];
__device__ __align__(16) int2  g_edge[N_EDGES];              // {src, dinv[src] bits}
__device__ __align__(16) float g_dinv[N_NODES];
__device__ __align__(16) float g_h1[(size_t)N_NODES * D1];
__device__ __align__(16) float g_z1[(size_t)N_NODES * D1];
__device__ __align__(16) float g_h2[(size_t)N_NODES * D2];
__device__ __align__(16) float g_gsum[NUM_GRAPHS * D2];
__device__ __align__(16) int   g_gcnt[NUM_GRAPHS];

// ---------------- init ----------------
__global__ void init_kernel() {
    int i = blockIdx.x * blockDim.x + threadIdx.x;
    int stride = gridDim.x * blockDim.x;
    for (int k = i; k < N_NODES; k += stride) g_deg[k] = 0;
    for (int k = i; k < NUM_GRAPHS * D2; k += stride) g_gsum[k] = 0.0f;
    if (i < NUM_GRAPHS) g_gcnt[i] = 0;
}

// ---------------- degree histogram over dst, 4 edges/thread ----------------
__global__ void count_kernel(const int* __restrict__ ei) {
    int i = blockIdx.x * blockDim.x + threadIdx.x;
    if (i < N_EDGES / 4) {
        int4 d = __ldg(reinterpret_cast<const int4*>(ei + N_EDGES) + i);
        atomicAdd(&g_deg[d.x], 1);
        atomicAdd(&g_deg[d.y], 1);
        atomicAdd(&g_deg[d.z], 1);
        atomicAdd(&g_deg[d.w], 1);
    }
}

// ---------------- single-block warp-shuffle scan ----------------
__global__ void scan_kernel() {
    __shared__ int warp_sums[32];
    int tid = threadIdx.x;            // 1024 threads
    int lane = tid & 31, wid = tid >> 5;
    int carry = 0;
    for (int base = 0; base < N_NODES; base += 1024) {
        int i = base + tid;
        int v = (i < N_NODES) ? g_deg[i] : 0;
        int x = v;
        #pragma unroll
        for (int off = 1; off < 32; off <<= 1) {
            int y = __shfl_up_sync(0xffffffffu, x, off);
            if (lane >= off) x += y;
        }
        if (lane == 31) warp_sums[wid] = x;
        __syncthreads();
        if (wid == 0) {
            int w = warp_sums[lane];
            #pragma unroll
            for (int off = 1; off < 32; off <<= 1) {
                int y = __shfl_up_sync(0xffffffffu, w, off);
                if (lane >= off) w += y;
            }
            warp_sums[lane] = w;
        }
        __syncthreads();
        int warp_prefix = (wid > 0) ? warp_sums[wid - 1] : 0;
        int incl = carry + warp_prefix + x;
        if (i < N_NODES) {
            g_csr_off[i + 1] = incl;
            g_csr_cur[i]     = incl - v;
            g_dinv[i]        = rsqrtf((float)(v + 1));
        }
        if (i == 0) g_csr_off[0] = 0;
        int tot = warp_sums[31];
        __syncthreads();
        carry += tot;
    }
}

// ---------------- CSR fill: 4 edges/thread, packed {src, w} per slot ----------------
__global__ void fill_kernel(const int* __restrict__ ei) {
    int i = blockIdx.x * blockDim.x + threadIdx.x;
    if (i < N_EDGES / 4) {
        int4 s4 = __ldg(reinterpret_cast<const int4*>(ei) + i);
        int4 d4 = __ldg(reinterpret_cast<const int4*>(ei + N_EDGES) + i);
        int slot;
        slot = atomicAdd(&g_csr_cur[d4.x], 1);
        g_edge[slot] = make_int2(s4.x, __float_as_int(g_dinv[s4.x]));
        slot = atomicAdd(&g_csr_cur[d4.y], 1);
        g_edge[slot] = make_int2(s4.y, __float_as_int(g_dinv[s4.y]));
        slot = atomicAdd(&g_csr_cur[d4.z], 1);
        g_edge[slot] = make_int2(s4.z, __float_as_int(g_dinv[s4.z]));
        slot = atomicAdd(&g_csr_cur[d4.w], 1);
        g_edge[slot] = make_int2(s4.w, __float_as_int(g_dinv[s4.w]));
    }
}

// ======= bf16 tensor-core GEMM (mma.sync m16n8k16), 128x64 CTA tile, 3 CTAs/SM =======
// 8 warps in 4(M) x 2(N); warp tile 32x32 (MT=2, NT=4) -> ~80 regs -> occupancy 3.
#define BM 128
#define BN 64
#define ASTR 20   // As word stride: A-frag LDS conflict-free, v4 STS aligned
#define BSTR 21   // Bs word stride: transpose STS conflict-free

__global__ __launch_bounds__(256, 3)
void gemm_bf16_kernel(const float* __restrict__ A, const float* __restrict__ B,
                      float* __restrict__ C, int M, int N, int K) {
    constexpr int MT = 2;                // m16 tiles per warp
    constexpr int NT = 4;                // n8 tiles per warp
    __shared__ uint32_t As[BM * ASTR];   // [row][k2] bf16x2, k2 = 0..15
    __shared__ uint32_t Bs[BN * BSTR];   // [col][k2] bf16x2 (transposed)

    int tid  = threadIdx.x;              // 256
    int lane = tid & 31, wid = tid >> 5; // 8 warps
    int wm = wid & 3, wn = wid >> 2;     // warp grid 4(M) x 2(N)
    int warp_row = wm * 32;
    int warp_col = wn * 32;
    int row0 = blockIdx.x * BM;
    int col0 = blockIdx.y * BN;
    int tig = lane & 3, grp = lane >> 2;

    float acc[MT][NT][4] = {};

    for (int k0 = 0; k0 < K; k0 += 32) {
        // ---- A chunk: 128 rows x 32 cols fp32 -> bf16x2, 2 iters x 8 floats/thread
        #pragma unroll
        for (int i = 0; i < 2; i++) {
            int idx = tid + (i << 8);
            int r  = idx >> 2;            // 0..127
            int c8 = (idx & 3) << 3;      // 0,8,16,24
            int gr = row0 + r;
            float4 v0 = make_float4(0.f,0.f,0.f,0.f), v1 = v0;
            if (gr < M) {
                const float4* ap = reinterpret_cast<const float4*>(&A[(size_t)gr * K + k0 + c8]);
                v0 = ap[0]; v1 = ap[1];
            }
            __nv_bfloat162 p0 = __float22bfloat162_rn(make_float2(v0.x, v0.y));
            __nv_bfloat162 p1 = __float22bfloat162_rn(make_float2(v0.z, v0.w));
            __nv_bfloat162 p2 = __float22bfloat162_rn(make_float2(v1.x, v1.y));
            __nv_bfloat162 p3 = __float22bfloat162_rn(make_float2(v1.z, v1.w));
            uint32_t* dst = &As[r * ASTR + (c8 >> 1)];
            *reinterpret_cast<uint4*>(dst) =
                make_uint4(*reinterpret_cast<uint32_t*>(&p0), *reinterpret_cast<uint32_t*>(&p1),
                           *reinterpret_cast<uint32_t*>(&p2), *reinterpret_cast<uint32_t*>(&p3));
        }
        // ---- B chunk transposed: Bs[n][k2] = {B[k0+2k2][n], B[k0+2k2+1][n]}; 4 iters
        #pragma unroll
        for (int i = 0; i < 4; i++) {
            int idx = tid + (i << 8);     // 0..1023
            int k2 = idx >> 6;            // 0..15
            int n  = idx & 63;
            const float* bp = &B[(size_t)(k0 + 2 * k2) * N + col0 + n];
            __nv_bfloat162 p = __float22bfloat162_rn(make_float2(bp[0], bp[N]));
            Bs[n * BSTR + k2] = *reinterpret_cast<uint32_t*>(&p);
        }
        __syncthreads();

        #pragma unroll
        for (int ks = 0; ks < 2; ks++) {  // two k16 steps per chunk
            int kw = ks << 3;             // word offset 0 or 8
            uint32_t af[MT][4], bf[NT][2];
            #pragma unroll
            for (int mt = 0; mt < MT; mt++) {
                int r = warp_row + mt * 16 + grp;
                af[mt][0] = As[r * ASTR + kw + tig];
                af[mt][1] = As[(r + 8) * ASTR + kw + tig];
                af[mt][2] = As[r * ASTR + kw + tig + 4];
                af[mt][3] = As[(r + 8) * ASTR + kw + tig + 4];
            }
            #pragma unroll
            for (int nt = 0; nt < NT; nt++) {
                int c = warp_col + nt * 8 + grp;
                bf[nt][0] = Bs[c * BSTR + kw + tig];
                bf[nt][1] = Bs[c * BSTR + kw + tig + 4];
            }
            #pragma unroll
            for (int mt = 0; mt < MT; mt++)
                #pragma unroll
                for (int nt = 0; nt < NT; nt++) {
                    asm volatile(
                        "mma.sync.aligned.m16n8k16.row.col.f32.bf16.bf16.f32 "
                        "{%0,%1,%2,%3}, {%4,%5,%6,%7}, {%8,%9}, {%0,%1,%2,%3};\n"
                        : "+f"(acc[mt][nt][0]), "+f"(acc[mt][nt][1]),
                          "+f"(acc[mt][nt][2]), "+f"(acc[mt][nt][3])
                        : "r"(af[mt][0]), "r"(af[mt][1]), "r"(af[mt][2]), "r"(af[mt][3]),
                          "r"(bf[nt][0]), "r"(bf[nt][1]));
                }
        }
        __syncthreads();
    }

    // epilogue: c0/c1 at (row, 2*tig), c2/c3 at (row+8, 2*tig)
    #pragma unroll
    for (int mt = 0; mt < MT; mt++) {
        int r_lo = row0 + warp_row + mt * 16 + grp;
        int r_hi = r_lo + 8;
        #pragma unroll
        for (int nt = 0; nt < NT; nt++) {
            int c = col0 + warp_col + nt * 8 + 2 * tig;
            if (r_lo < M) {
                float2 v = make_float2(acc[mt][nt][0], acc[mt][nt][1]);
                *reinterpret_cast<float2*>(&C[(size_t)r_lo * N + c]) = v;
            }
            if (r_hi < M) {
                float2 v = make_float2(acc[mt][nt][2], acc[mt][nt][3]);
                *reinterpret_cast<float2*>(&C[(size_t)r_hi * N + c]) = v;
            }
        }
    }
}

// ---------------- gather aggregation (float4, packed edges, unroll-2) ----------------
template <int F, bool POOL>
__global__ void aggregate_kernel(const float* __restrict__ H, const float* __restrict__ bias,
                                 float* __restrict__ Z, const int* __restrict__ batch) {
    constexpr int TF  = F / 4;
    constexpr int NPB = 256 / TF;
    int node = blockIdx.x * NPB + threadIdx.y;
    if (node >= N_NODES) return;
    int t = threadIdx.x;
    const float4* H4 = reinterpret_cast<const float4*>(H);

    float di = g_dinv[node];
    float4 h = __ldg(&H4[(size_t)node * TF + t]);
    float4 acc = make_float4(di * h.x, di * h.y, di * h.z, di * h.w);

    int e = g_csr_off[node], e1 = g_csr_off[node + 1];
    for (; e + 1 < e1; e += 2) {
        int2 r0 = __ldg(&g_edge[e]);
        int2 r1 = __ldg(&g_edge[e + 1]);
        float4 h0 = __ldg(&H4[(size_t)r0.x * TF + t]);
        float4 h1 = __ldg(&H4[(size_t)r1.x * TF + t]);
        float w0 = __int_as_float(r0.y), w1 = __int_as_float(r1.y);
        acc.x = fmaf(w0, h0.x, fmaf(w1, h1.x, acc.x));
        acc.y = fmaf(w0, h0.y, fmaf(w1, h1.y, acc.y));
        acc.z = fmaf(w0, h0.z, fmaf(w1, h1.z, acc.z));
        acc.w = fmaf(w0, h0.w, fmaf(w1, h1.w, acc.w));
    }
    if (e < e1) {
        int2 r0 = __ldg(&g_edge[e]);
        float4 h0 = __ldg(&H4[(size_t)r0.x * TF + t]);
        float w0 = __int_as_float(r0.y);
        acc.x = fmaf(w0, h0.x, acc.x);
        acc.y = fmaf(w0, h0.y, acc.y);
        acc.z = fmaf(w0, h0.z, acc.z);
        acc.w = fmaf(w0, h0.w, acc.w);
    }
    float4 b4 = __ldg(&reinterpret_cast<const float4*>(bias)[t]);
    float4 v;
    v.x = fmaxf(fmaf(di, acc.x, b4.x), 0.0f);
    v.y = fmaxf(fmaf(di, acc.y, b4.y), 0.0f);
    v.z = fmaxf(fmaf(di, acc.z, b4.z), 0.0f);
    v.w = fmaxf(fmaf(di, acc.w, b4.w), 0.0f);

    if (POOL) {
        int g = batch[node];
        float* gp = &g_gsum[g * F + 4 * t];
        atomicAdd(gp + 0, v.x);
        atomicAdd(gp + 1, v.y);
        atomicAdd(gp + 2, v.z);
        atomicAdd(gp + 3, v.w);
        if (t == 0) atomicAdd(&g_gcnt[g], 1);
    } else {
        reinterpret_cast<float4*>(Z)[(size_t)node * TF + t] = v;
    }
}

// ---------------- head MLP ----------------
__global__ void final_kernel(const float* __restrict__ Wl1, const float* __restrict__ bl1,
                             const float* __restrict__ Wl2, const float* __restrict__ bl2,
                             float* __restrict__ out) {
    int g = blockIdx.x;
    int j = threadIdx.x;    // 64
    __shared__ float sg[D2];
    __shared__ float sr[64];
    float cnt = (float)max(g_gcnt[g], 1);
    for (int k = j; k < D2; k += 64) sg[k] = g_gsum[g * D2 + k] / cnt;
    __syncthreads();
    float acc = bl1[j];
    #pragma unroll 8
    for (int k = 0; k < D2; k++) acc = fmaf(sg[k], Wl1[k * 64 + j], acc);
    acc = fmaxf(acc, 0.0f);
    sr[j] = acc * Wl2[j];
    #pragma unroll
    for (int off = 32; off > 0; off >>= 1) {
        __syncthreads();
        if (j < off) sr[j] += sr[j + off];
    }
    __syncthreads();
    if (j == 0) out[g] = 1.0f / (1.0f + expf(-(sr[0] + bl2[0])));
}

// ---------------- launch: fork CSR build || GEMM1, join before agg1 ----------------
extern "C" void kernel_launch(void* const* d_in, const int* in_sizes, int n_in,
                              void* d_out, int out_size) {
    const float* x     = (const float*)d_in[0];
    const int*   ei    = (const int*)d_in[1];     // int32 (JAX x64 disabled)
    const int*   batch = (const int*)d_in[2];     // int32
    const float* W1  = (const float*)d_in[3];
    const float* b1  = (const float*)d_in[4];
    const float* W2  = (const float*)d_in[5];
    const float* b2  = (const float*)d_in[6];
    const float* Wl1 = (const float*)d_in[7];
    const float* bl1 = (const float*)d_in[8];
    const float* Wl2 = (const float*)d_in[9];
    const float* bl2 = (const float*)d_in[10];
    float* out = (float*)d_out;

    void* p;
    cudaGetSymbolAddress(&p, g_h1); float* h1 = (float*)p;
    cudaGetSymbolAddress(&p, g_z1); float* z1 = (float*)p;
    cudaGetSymbolAddress(&p, g_h2); float* h2 = (float*)p;

    static cudaStream_t s1 = nullptr;
    static cudaEvent_t evFork = nullptr, evJoin = nullptr;
    if (s1 == nullptr) {
        cudaStreamCreateWithFlags(&s1, cudaStreamNonBlocking);
        cudaEventCreateWithFlags(&evFork, cudaEventDisableTiming);
        cudaEventCreateWithFlags(&evJoin, cudaEventDisableTiming);
    }

    // fork
    cudaEventRecord(evFork, 0);
    cudaStreamWaitEvent(s1, evFork, 0);

    // s1: CSR build chain
    init_kernel<<<64, 256, 0, s1>>>();
    count_kernel<<<(N_EDGES / 4 + 255) / 256, 256, 0, s1>>>(ei);
    scan_kernel<<<1, 1024, 0, s1>>>();
    fill_kernel<<<(N_EDGES / 4 + 255) / 256, 256, 0, s1>>>(ei);
    cudaEventRecord(evJoin, s1);

    // main: GEMM1 (128x64 tiles, 3 CTAs/SM -> 628 CTAs over capacity 444)
    gemm_bf16_kernel<<<dim3((N_NODES + BM - 1) / BM, D1 / BN), 256>>>(
        x, W1, h1, N_NODES, D1, D0);

    // join: agg1 needs both CSR and h1
    cudaStreamWaitEvent(0, evJoin, 0);

    {
        dim3 blk(D1 / 4, 256 / (D1 / 4));         // (64, 4)
        aggregate_kernel<D1, false><<<(N_NODES + 3) / 4, blk>>>(h1, b1, z1, nullptr);
    }

    // GEMM2 (128x64 tiles -> 314 CTAs, sub-wave at occupancy 3)
    gemm_bf16_kernel<<<dim3((N_NODES + BM - 1) / BM, D2 / BN), 256>>>(
        z1, W2, h2, N_NODES, D2, D1);

    {
        dim3 blk(D2 / 4, 256 / (D2 / 4));         // (32, 8)
        aggregate_kernel<D2, true><<<(N_NODES + 7) / 8, blk>>>(h2, b2, nullptr, batch);
    }

    final_kernel<<<NUM_GRAPHS, 64>>>(Wl1, bl1, Wl2, bl2, out);
}